// round 1
// baseline (speedup 1.0000x reference)
#include <cuda_runtime.h>
#include <cstdint>

// Problem constants: x [NB, C, H, W], T = H*W
constexpr int kNB  = 8;
constexpr int kC   = 512;
constexpr int kT   = 4096;
constexpr int kG   = 32;
constexpr int kCPG = kC / kG;          // 16 channels per group
constexpr float kEPS = 1e-5f;

// -------------------- scratch (static .bss, no allocations) ----------------
__device__ float g_mean[kNB * kG];
__device__ float g_rstd[kNB * kG];
__device__ float g_h  [(size_t)kNB * kC * kT];          //  67 MB  normalized input
__device__ float g_qkv[(size_t)kNB * 3 * kC * kT];      // 201 MB  q|k|v in [d][t]
__device__ float g_S  [(size_t)kNB * kT * kT];          // 537 MB  attention logits/probs
__device__ float g_o  [(size_t)kNB * kC * kT];          //  67 MB  attn output [c][t]

// -------------------- GroupNorm statistics ---------------------------------
// One block per (n,g). Channels of a group are contiguous, so the slab is
// 16*4096 = 65536 contiguous floats starting at (n*kG+g)*65536.
__global__ void gn_stats_kernel(const float* __restrict__ x)
{
    const int b = blockIdx.x;                       // n*kG + g
    const float4* p = (const float4*)(x + (size_t)b * (kCPG * kT));
    float s = 0.f, ss = 0.f;
    for (int l = threadIdx.x; l < kCPG * kT / 4; l += 256) {
        float4 v = p[l];
        s  += v.x + v.y + v.z + v.w;
        ss += v.x*v.x + v.y*v.y + v.z*v.z + v.w*v.w;
    }
    __shared__ float rs[8], rss[8];
    for (int o = 16; o; o >>= 1) {
        s  += __shfl_xor_sync(0xffffffffu, s,  o);
        ss += __shfl_xor_sync(0xffffffffu, ss, o);
    }
    const int w = threadIdx.x >> 5, lane = threadIdx.x & 31;
    if (lane == 0) { rs[w] = s; rss[w] = ss; }
    __syncthreads();
    if (threadIdx.x == 0) {
        float S = 0.f, SS = 0.f;
        for (int i = 0; i < 8; i++) { S += rs[i]; SS += rss[i]; }
        const float inv = 1.f / (kCPG * kT);
        const float m = S * inv;
        const float var = SS * inv - m * m;
        g_mean[b] = m;
        g_rstd[b] = rsqrtf(var + kEPS);
    }
}

// -------------------- GroupNorm apply: h = (x-m)*rstd*w + b -----------------
__global__ void gn_apply_kernel(const float* __restrict__ x,
                                const float* __restrict__ gw,
                                const float* __restrict__ gb)
{
    const size_t f = (size_t)blockIdx.x * blockDim.x + threadIdx.x;   // float4 idx
    const size_t e = f * 4;
    if (e >= (size_t)kNB * kC * kT) return;
    const int c = (int)((e / kT) % kC);
    const int b = (int)(e / ((size_t)kCPG * kT));                     // n*kG+g
    const float r  = g_rstd[b];
    const float sc = gw[c] * r;
    const float sh = gb[c] - g_mean[b] * sc;
    float4 v = *(const float4*)(x + e);
    v.x = v.x * sc + sh; v.y = v.y * sc + sh;
    v.z = v.z * sc + sh; v.w = v.w * sc + sh;
    *(float4*)(g_h + e) = v;
}

// -------------------- generic tiled SGEMM ----------------------------------
// C[i,j] = sum_k A[i*sAi + k*sAk] * B[k*sBk + j*sBj]
//   A_KC: A contiguous along k (sAk==1), else contiguous along i (sAi==1)
//   B_JC: B contiguous along j (sBj==1), else contiguous along k (sBk==1)
//   EPI:  0 plain, 1 +bias[i], 2 +bias[i]+resid[i*ldc+j]
// 256 threads, thread (ty,tx) of 16x16 computes a TMxTN register tile.
template<int BM, int BN, int BK, bool A_KC, bool B_JC, int EPI>
__global__ __launch_bounds__(256)
void gemm_kernel(const float* __restrict__ A, const float* __restrict__ B,
                 float* __restrict__ Cc,
                 int M, int N, int K,
                 int sAi, int sAk, int sBk, int sBj, int ldc,
                 size_t strA, size_t strB, size_t strC,
                 const float* __restrict__ bias,
                 const float* __restrict__ resid, size_t strR)
{
    constexpr int TM = BM / 16, TN = BN / 16;
    constexpr int BMp = BM + 4, BNp = BN + 4;
    __shared__ float As[BK][BMp];
    __shared__ float Bs[BK][BNp];

    A  += (size_t)blockIdx.z * strA;
    B  += (size_t)blockIdx.z * strB;
    Cc += (size_t)blockIdx.z * strC;
    const float* R = (EPI == 2) ? resid + (size_t)blockIdx.z * strR : nullptr;

    const int bi = blockIdx.y * BM;
    const int bj = blockIdx.x * BN;
    const int tid = threadIdx.x;
    const int tx = tid & 15, ty = tid >> 4;

    float acc[TM][TN];
#pragma unroll
    for (int i = 0; i < TM; i++)
#pragma unroll
        for (int j = 0; j < TN; j++) acc[i][j] = 0.f;

    for (int k0 = 0; k0 < K; k0 += BK) {
        // ---- load A tile (BM x BK) into As[k][i]
        if (A_KC) {
#pragma unroll
            for (int l = tid; l < BM * BK / 4; l += 256) {
                const int i  = l / (BK / 4);
                const int kc = (l % (BK / 4)) * 4;
                float4 v = *(const float4*)&A[(size_t)(bi + i) * sAi + (k0 + kc)];
                As[kc + 0][i] = v.x; As[kc + 1][i] = v.y;
                As[kc + 2][i] = v.z; As[kc + 3][i] = v.w;
            }
        } else {
#pragma unroll
            for (int l = tid; l < BM * BK / 4; l += 256) {
                const int i4 = (l % (BM / 4)) * 4;
                const int k  = l / (BM / 4);
                *(float4*)&As[k][i4] =
                    *(const float4*)&A[(size_t)(k0 + k) * sAk + (bi + i4)];
            }
        }
        // ---- load B tile (BK x BN) into Bs[k][j]
        if (B_JC) {
#pragma unroll
            for (int l = tid; l < BN * BK / 4; l += 256) {
                const int j4 = (l % (BN / 4)) * 4;
                const int k  = l / (BN / 4);
                *(float4*)&Bs[k][j4] =
                    *(const float4*)&B[(size_t)(k0 + k) * sBk + (bj + j4)];
            }
        } else {
#pragma unroll
            for (int l = tid; l < BN * BK / 4; l += 256) {
                const int j  = l / (BK / 4);
                const int kc = (l % (BK / 4)) * 4;
                float4 v = *(const float4*)&B[(size_t)(bj + j) * sBj + (k0 + kc)];
                Bs[kc + 0][j] = v.x; Bs[kc + 1][j] = v.y;
                Bs[kc + 2][j] = v.z; Bs[kc + 3][j] = v.w;
            }
        }
        __syncthreads();

#pragma unroll
        for (int k = 0; k < BK; k++) {
            float a[TM], b[TN];
#pragma unroll
            for (int m = 0; m < TM; m += 4)
                *(float4*)&a[m] = *(const float4*)&As[k][ty * TM + m];
#pragma unroll
            for (int n2 = 0; n2 < TN; n2 += 4)
                *(float4*)&b[n2] = *(const float4*)&Bs[k][tx * TN + n2];
#pragma unroll
            for (int i = 0; i < TM; i++)
#pragma unroll
                for (int j = 0; j < TN; j++)
                    acc[i][j] = fmaf(a[i], b[j], acc[i][j]);
        }
        __syncthreads();
    }

    // ---- epilogue
#pragma unroll
    for (int i = 0; i < TM; i++) {
        const int gi = bi + ty * TM + i;
        const float bv = (EPI >= 1) ? bias[gi] : 0.f;
        const size_t base = (size_t)gi * ldc + bj + tx * TN;
#pragma unroll
        for (int j = 0; j < TN; j += 4) {
            float4 v;
            v.x = acc[i][j + 0] + bv; v.y = acc[i][j + 1] + bv;
            v.z = acc[i][j + 2] + bv; v.w = acc[i][j + 3] + bv;
            if (EPI == 2) {
                float4 r = *(const float4*)&R[base + j];
                v.x += r.x; v.y += r.y; v.z += r.z; v.w += r.w;
            }
            *(float4*)&Cc[base + j] = v;
        }
    }
}

// -------------------- row softmax over g_S ---------------------------------
// One block per attention row (NB*T rows). Scale by C^-0.5 fused in.
__global__ void softmax_kernel()
{
    __shared__ float srow[kT];
    __shared__ float red[8];
    float* row = g_S + (size_t)blockIdx.x * kT;
    const float sc = 0.044194173824159216f;      // 512^-0.5
    const int w = threadIdx.x >> 5, lane = threadIdx.x & 31;

    float m = -1e30f;
    for (int l = threadIdx.x; l < kT / 4; l += 256) {
        float4 v = *(const float4*)&row[l * 4];
        v.x *= sc; v.y *= sc; v.z *= sc; v.w *= sc;
        *(float4*)&srow[l * 4] = v;
        m = fmaxf(m, fmaxf(fmaxf(v.x, v.y), fmaxf(v.z, v.w)));
    }
    for (int o = 16; o; o >>= 1) m = fmaxf(m, __shfl_xor_sync(0xffffffffu, m, o));
    if (lane == 0) red[w] = m;
    __syncthreads();
    m = red[0];
#pragma unroll
    for (int i = 1; i < 8; i++) m = fmaxf(m, red[i]);

    float s = 0.f;
    for (int l = threadIdx.x; l < kT / 4; l += 256) {
        float4 v = *(const float4*)&srow[l * 4];
        v.x = __expf(v.x - m); v.y = __expf(v.y - m);
        v.z = __expf(v.z - m); v.w = __expf(v.w - m);
        *(float4*)&srow[l * 4] = v;
        s += v.x + v.y + v.z + v.w;
    }
    for (int o = 16; o; o >>= 1) s += __shfl_xor_sync(0xffffffffu, s, o);
    __syncthreads();                      // everyone done reading red (max)
    if (lane == 0) red[w] = s;
    __syncthreads();
    s = 0.f;
#pragma unroll
    for (int i = 0; i < 8; i++) s += red[i];
    const float inv = 1.f / s;

    for (int l = threadIdx.x; l < kT / 4; l += 256) {
        float4 v = *(const float4*)&srow[l * 4];
        v.x *= inv; v.y *= inv; v.z *= inv; v.w *= inv;
        *(float4*)&row[l * 4] = v;
    }
}

// -------------------- launch -----------------------------------------------
extern "C" void kernel_launch(void* const* d_in, const int* in_sizes, int n_in,
                              void* d_out, int out_size)
{
    const float* x      = (const float*)d_in[0];
    const float* gn_w   = (const float*)d_in[1];
    const float* gn_b   = (const float*)d_in[2];
    const float* qkv_w  = (const float*)d_in[3];
    const float* qkv_b  = (const float*)d_in[4];
    const float* proj_w = (const float*)d_in[5];
    const float* proj_b = (const float*)d_in[6];
    float* out = (float*)d_out;

    float *h, *qkv, *S, *o;
    cudaGetSymbolAddress((void**)&h,   g_h);
    cudaGetSymbolAddress((void**)&qkv, g_qkv);
    cudaGetSymbolAddress((void**)&S,   g_S);
    cudaGetSymbolAddress((void**)&o,   g_o);

    // 1) GroupNorm
    gn_stats_kernel<<<kNB * kG, 256>>>(x);
    gn_apply_kernel<<<((size_t)kNB * kC * kT / 4 + 255) / 256, 256>>>(x, gn_w, gn_b);

    // 2) QKV projection: qkv[n][d][t] = sum_c W[d][c] * h[n][c][t] + b[d]
    //    A row-major (k-contig), B j-contig (t contiguous).
    gemm_kernel<128, 128, 8, true, true, 1>
        <<<dim3(kT / 128, (3 * kC) / 128, kNB), 256>>>(
            qkv_w, h, qkv, 3 * kC, kT, kC,
            /*sAi*/kC, /*sAk*/1, /*sBk*/kT, /*sBj*/1, /*ldc*/kT,
            0, (size_t)kC * kT, (size_t)3 * kC * kT,
            qkv_b, nullptr, 0);

    // 3) Logits: S[n][i][j] = sum_c q[c][i] * k[c][j]   (TN: both i/j contiguous)
    gemm_kernel<128, 128, 8, false, true, 0>
        <<<dim3(kT / 128, kT / 128, kNB), 256>>>(
            qkv, qkv + (size_t)kC * kT, S, kT, kT, kC,
            /*sAi*/1, /*sAk*/kT, /*sBk*/kT, /*sBj*/1, /*ldc*/kT,
            (size_t)3 * kC * kT, (size_t)3 * kC * kT, (size_t)kT * kT,
            nullptr, nullptr, 0);

    // 4) Softmax rows (scale fused)
    softmax_kernel<<<kNB * kT, 256>>>();

    // 5) o[n][c][q] = sum_k v[c][k] * P[q][k]   (NT: A k-contig, B k-contig)
    gemm_kernel<64, 128, 8, true, false, 0>
        <<<dim3(kT / 128, kC / 64, kNB), 256>>>(
            qkv + (size_t)2 * kC * kT, S, o, kC, kT, kT,
            /*sAi*/kT, /*sAk*/1, /*sBk*/1, /*sBj*/kT, /*ldc*/kT,
            (size_t)3 * kC * kT, (size_t)kT * kT, (size_t)kC * kT,
            nullptr, nullptr, 0);

    // 6) out[n][d][t] = x + sum_c proj_w[d][c] * o[c][t] + proj_b[d]
    gemm_kernel<64, 128, 8, true, true, 2>
        <<<dim3(kT / 128, kC / 64, kNB), 256>>>(
            proj_w, o, out, kC, kT, kC,
            /*sAi*/kC, /*sAk*/1, /*sBk*/kT, /*sBj*/1, /*ldc*/kT,
            0, (size_t)kC * kT, (size_t)kC * kT,
            proj_b, x, (size_t)kC * kT);
}

// round 5
// speedup vs baseline: 2.8125x; 2.8125x over previous
#include <cuda_runtime.h>
#include <cuda_bf16.h>
#include <cstdint>

// Problem constants: x [NB, C, H, W], T = H*W
constexpr int kNB  = 8;
constexpr int kC   = 512;
constexpr int kT   = 4096;
constexpr int kG   = 32;
constexpr int kCPG = kC / kG;
constexpr float kEPS = 1e-5f;

// -------------------- scratch (static .bss, no allocations) ----------------
__device__ float g_mean[kNB * kG];
__device__ float g_rstd[kNB * kG];
__device__ float g_h  [(size_t)kNB * kC * kT];          // normalized input [c][t]
// qkv: q TRANSPOSED [t][c] | k [c][t] | v TRANSPOSED [t][c]
__device__ float g_qkv[(size_t)kNB * 3 * kC * kT];
__device__ float g_S  [(size_t)kNB * kT * kT];          // logits / probs
__device__ float g_o  [(size_t)kNB * kC * kT];          // attn out [t][c]

// ======================= helpers ===========================================
__device__ __forceinline__ uint32_t smem_u32(const void* p) {
    uint32_t a;
    asm("{ .reg .u64 t; cvta.to.shared.u64 t, %1; cvt.u32.u64 %0, t; }"
        : "=r"(a) : "l"(p));
    return a;
}
__device__ __forceinline__ void ldsm4(uint32_t* r, uint32_t addr) {
    asm volatile("ldmatrix.sync.aligned.m8n8.x4.shared.b16 {%0,%1,%2,%3}, [%4];"
        : "=r"(r[0]), "=r"(r[1]), "=r"(r[2]), "=r"(r[3]) : "r"(addr));
}
__device__ __forceinline__ void ldsm4t(uint32_t* r, uint32_t addr) {
    asm volatile("ldmatrix.sync.aligned.m8n8.x4.trans.shared.b16 {%0,%1,%2,%3}, [%4];"
        : "=r"(r[0]), "=r"(r[1]), "=r"(r[2]), "=r"(r[3]) : "r"(addr));
}
__device__ __forceinline__ void mma16816(float* d, const uint32_t* a,
                                         uint32_t b0, uint32_t b1) {
    asm volatile("mma.sync.aligned.m16n8k16.row.col.f32.bf16.bf16.f32 "
        "{%0,%1,%2,%3}, {%4,%5,%6,%7}, {%8,%9}, {%0,%1,%2,%3};"
        : "+f"(d[0]), "+f"(d[1]), "+f"(d[2]), "+f"(d[3])
        : "r"(a[0]), "r"(a[1]), "r"(a[2]), "r"(a[3]), "r"(b0), "r"(b1));
}
// split fp32 float4 -> hi/lo bf16 quads at hp/lp (8B each)
__device__ __forceinline__ void cvt8(__nv_bfloat16* hp, __nv_bfloat16* lp, float4 v) {
    float2 v01{v.x, v.y}, v23{v.z, v.w};
    __nv_bfloat162 h01 = __float22bfloat162_rn(v01);
    __nv_bfloat162 h23 = __float22bfloat162_rn(v23);
    float2 l01{v.x - __bfloat162float(h01.x), v.y - __bfloat162float(h01.y)};
    float2 l23{v.z - __bfloat162float(h23.x), v.w - __bfloat162float(h23.y)};
    __nv_bfloat162 L01 = __float22bfloat162_rn(l01);
    __nv_bfloat162 L23 = __float22bfloat162_rn(l23);
    *(__nv_bfloat162*)hp       = h01;
    *(__nv_bfloat162*)(hp + 2) = h23;
    *(__nv_bfloat162*)lp       = L01;
    *(__nv_bfloat162*)(lp + 2) = L23;
}

// ======================= GroupNorm =========================================
__global__ void gn_stats_kernel(const float* __restrict__ x)
{
    const int b = blockIdx.x;
    const float4* p = (const float4*)(x + (size_t)b * (kCPG * kT));
    float s = 0.f, ss = 0.f;
    for (int l = threadIdx.x; l < kCPG * kT / 4; l += 256) {
        float4 v = p[l];
        s  += v.x + v.y + v.z + v.w;
        ss += v.x*v.x + v.y*v.y + v.z*v.z + v.w*v.w;
    }
    __shared__ float rs[8], rss[8];
    for (int o = 16; o; o >>= 1) {
        s  += __shfl_xor_sync(0xffffffffu, s,  o);
        ss += __shfl_xor_sync(0xffffffffu, ss, o);
    }
    const int w = threadIdx.x >> 5, lane = threadIdx.x & 31;
    if (lane == 0) { rs[w] = s; rss[w] = ss; }
    __syncthreads();
    if (threadIdx.x == 0) {
        float S = 0.f, SS = 0.f;
        for (int i = 0; i < 8; i++) { S += rs[i]; SS += rss[i]; }
        const float inv = 1.f / (kCPG * kT);
        const float m = S * inv;
        g_mean[b] = m;
        g_rstd[b] = rsqrtf(SS * inv - m * m + kEPS);
    }
}

__global__ void gn_apply_kernel(const float* __restrict__ x,
                                const float* __restrict__ gw,
                                const float* __restrict__ gb)
{
    const size_t f = (size_t)blockIdx.x * blockDim.x + threadIdx.x;
    const size_t e = f * 4;
    if (e >= (size_t)kNB * kC * kT) return;
    const int c = (int)((e / kT) % kC);
    const int b = (int)(e / ((size_t)kCPG * kT));
    const float r  = g_rstd[b];
    const float sc = gw[c] * r;
    const float sh = gb[c] - g_mean[b] * sc;
    float4 v = *(const float4*)(x + e);
    v.x = v.x * sc + sh; v.y = v.y * sc + sh;
    v.z = v.z * sc + sh; v.w = v.w * sc + sh;
    *(float4*)(g_h + e) = v;
}

// ======================= mma.sync GEMM =====================================
// D[128x128 tile] = A[m][k] * B;  A fp32 k-contig rows (lda).
//  BJC=true : B[k][n], n contiguous (ldb)
//  BJC=false: B[n][k], k contiguous (ldb)  (transposed into smem)
// EPI: 0 plain; 2 +bias[m]+resid; 3 QKV routing (q,v transposed via smem stage)
// smem per stage (bf16 elems): Ahi 128*40 | Alo | Bhi 32*136 | Blo
constexpr int kAW = 40, kBW = 136;
constexpr int kAhi = 0, kAlo = 5120, kBhi = 10240, kBlo = 14592;
constexpr int kSS  = 18944;                       // stage elems
constexpr int kSmemBytes = 2 * kSS * 2;           // 75776 B

template<bool BJC, int EPI>
__global__ __launch_bounds__(256)
void mma_gemm(const float* __restrict__ A, int lda, size_t sA,
              const float* __restrict__ B, int ldb, size_t sB,
              float* __restrict__ C, int ldc, size_t sC,
              const float* __restrict__ bias,
              const float* __restrict__ resid, int K)
{
    extern __shared__ char smem[];
    __nv_bfloat16* sb = (__nv_bfloat16*)smem;
    const uint32_t sbase = smem_u32(smem);

    const int tid = threadIdx.x;
    const int lane = tid & 31, wid = tid >> 5;
    const int wm = wid >> 1, wn = wid & 1;

    A += (size_t)blockIdx.z * sA;
    B += (size_t)blockIdx.z * sB;
    C += (size_t)blockIdx.z * sC;
    const int bi = blockIdx.y * 128, bj = blockIdx.x * 128;
    const float* Ab = A + (size_t)bi * lda;
    const float* Bb = BJC ? (B + bj) : (B + (size_t)bj * ldb);

    float acc[2][8][4];
#pragma unroll
    for (int m = 0; m < 2; m++)
#pragma unroll
        for (int n = 0; n < 8; n++)
#pragma unroll
            for (int q = 0; q < 4; q++) acc[m][n][q] = 0.f;

    float4 ar[4], br[4];

    auto ldgA = [&](int k0) {
#pragma unroll
        for (int j = 0; j < 4; j++) {
            const int idx = tid + j * 256, r = idx >> 3, kq = idx & 7;
            ar[j] = *(const float4*)&Ab[(size_t)r * lda + k0 + kq * 4];
        }
    };
    auto ldgB = [&](int k0) {
        if (BJC) {
#pragma unroll
            for (int j = 0; j < 4; j++) {
                const int idx = tid + j * 256, kr = idx >> 5, nq = idx & 31;
                br[j] = *(const float4*)&Bb[(size_t)(k0 + kr) * ldb + nq * 4];
            }
        } else {
            const int ng = tid >> 3, kq = tid & 7;
#pragma unroll
            for (int j = 0; j < 4; j++)
                br[j] = *(const float4*)&Bb[(size_t)(ng * 4 + j) * ldb + k0 + kq * 4];
        }
    };
    auto sts = [&](int buf) {
        __nv_bfloat16* ah = sb + buf * kSS + kAhi;
        __nv_bfloat16* al = sb + buf * kSS + kAlo;
        __nv_bfloat16* bh = sb + buf * kSS + kBhi;
        __nv_bfloat16* bl = sb + buf * kSS + kBlo;
#pragma unroll
        for (int j = 0; j < 4; j++) {
            const int idx = tid + j * 256, r = idx >> 3, kq = idx & 7;
            cvt8(ah + r * kAW + kq * 4, al + r * kAW + kq * 4, ar[j]);
        }
        if (BJC) {
#pragma unroll
            for (int j = 0; j < 4; j++) {
                const int idx = tid + j * 256, kr = idx >> 5, nq = idx & 31;
                cvt8(bh + kr * kBW + nq * 4, bl + kr * kBW + nq * 4, br[j]);
            }
        } else {
            const int ng = tid >> 3, kq = tid & 7;
            const float* f = (const float*)br;
#pragma unroll
            for (int c = 0; c < 4; c++) {
                float4 t{f[c], f[4 + c], f[8 + c], f[12 + c]};
                cvt8(bh + (kq * 4 + c) * kBW + ng * 4,
                     bl + (kq * 4 + c) * kBW + ng * 4, t);
            }
        }
    };
    auto compute = [&](int buf) {
        const uint32_t ah = sbase + (buf * kSS + kAhi) * 2;
        const uint32_t al = sbase + (buf * kSS + kAlo) * 2;
        const uint32_t bh = sbase + (buf * kSS + kBhi) * 2;
        const uint32_t bl = sbase + (buf * kSS + kBlo) * 2;
#pragma unroll
        for (int kk = 0; kk < 32; kk += 16) {
            uint32_t Ahf[2][4], Alf[2][4], Bhf[4][4], Blf[4][4];
            const int arow = wm * 32 + (lane & 15);
            const int acol = kk + (lane >> 4) * 8;
#pragma unroll
            for (int mt = 0; mt < 2; mt++) {
                const uint32_t off = ((arow + mt * 16) * kAW + acol) * 2;
                ldsm4(Ahf[mt], ah + off);
                ldsm4(Alf[mt], al + off);
            }
            const int brow = kk + (lane & 15);
            const int bcol = wn * 64 + (lane >> 4) * 8;
#pragma unroll
            for (int g = 0; g < 4; g++) {
                const uint32_t off = (brow * kBW + bcol + g * 16) * 2;
                ldsm4t(Bhf[g], bh + off);
                ldsm4t(Blf[g], bl + off);
            }
#pragma unroll
            for (int mt = 0; mt < 2; mt++)
#pragma unroll
                for (int nt = 0; nt < 8; nt++) {
                    const int g = nt >> 1, h = (nt & 1) * 2;
                    mma16816(acc[mt][nt], Ahf[mt], Bhf[g][h], Bhf[g][h + 1]);
                    mma16816(acc[mt][nt], Ahf[mt], Blf[g][h], Blf[g][h + 1]);
                    mma16816(acc[mt][nt], Alf[mt], Bhf[g][h], Bhf[g][h + 1]);
                }
        }
    };

    const int nst = K / 32;
    ldgA(0); ldgB(0); sts(0);
    __syncthreads();
    for (int s = 0; s < nst; ++s) {
        if (s + 1 < nst) { ldgA((s + 1) * 32); ldgB((s + 1) * 32); }
        compute(s & 1);
        __syncthreads();
        if (s + 1 < nst) { sts((s + 1) & 1); __syncthreads(); }
    }

    // ------------------- epilogue ------------------------------------------
    if (EPI == 3 && (bi < 512 || bi >= 1024)) {
        // q / v blocks: stage to smem, write transposed [t][c] coalesced
        float* sf = (float*)smem;                   // [col 128][136]
#pragma unroll
        for (int mt = 0; mt < 2; mt++) {
            const int rl = wm * 32 + mt * 16 + (lane >> 2);
            const float bv0 = bias[bi + rl], bv8 = bias[bi + rl + 8];
#pragma unroll
            for (int nt = 0; nt < 8; nt++) {
                const int cl = wn * 64 + nt * 8 + (lane & 3) * 2;
                sf[(size_t)cl * 136 + rl]            = acc[mt][nt][0] + bv0;
                sf[(size_t)(cl + 1) * 136 + rl]      = acc[mt][nt][1] + bv0;
                sf[(size_t)cl * 136 + rl + 8]        = acc[mt][nt][2] + bv8;
                sf[(size_t)(cl + 1) * 136 + rl + 8]  = acc[mt][nt][3] + bv8;
            }
        }
        __syncthreads();
        float* outT = (bi < 512) ? C : (C + 2 * (size_t)kC * kT);
        const int coff = (bi < 512) ? bi : (bi - 1024);
        for (int i2 = tid; i2 < 4096; i2 += 256) {
            const int j = i2 >> 5, rq = i2 & 31;
            float4 v = *(float4*)&sf[(size_t)j * 136 + rq * 4];
            *(float4*)&outT[(size_t)(bj + j) * kC + coff + rq * 4] = v;
        }
        return;
    }

#pragma unroll
    for (int mt = 0; mt < 2; mt++) {
        const int rl = wm * 32 + mt * 16 + (lane >> 2);
        float bv0 = 0.f, bv8 = 0.f;
        if (EPI == 2 || EPI == 3) { bv0 = bias[bi + rl]; bv8 = bias[bi + rl + 8]; }
        float* Crow;
        if (EPI == 3) {     // k block: [c][t] at C + CT, row = bi-512+rl
            Crow = C + (size_t)kC * kT + (size_t)(bi - 512 + rl) * kT + bj;
        } else {
            Crow = C + (size_t)(bi + rl) * ldc + bj;
        }
        const int ldr = (EPI == 3) ? kT : ldc;
#pragma unroll
        for (int nt = 0; nt < 8; nt++) {
            const int cl = wn * 64 + nt * 8 + (lane & 3) * 2;
            float2 v0{acc[mt][nt][0] + bv0, acc[mt][nt][1] + bv0};
            float2 v1{acc[mt][nt][2] + bv8, acc[mt][nt][3] + bv8};
            if (EPI == 2) {
                const float* rp = resid + (size_t)blockIdx.z * sC
                                + (size_t)(bi + rl) * ldc + bj;
                float2 r0 = *(const float2*)&rp[cl];
                float2 r1 = *(const float2*)&rp[(size_t)8 * ldc + cl];
                v0.x += r0.x; v0.y += r0.y; v1.x += r1.x; v1.y += r1.y;
            }
            *(float2*)&Crow[cl] = v0;
            *(float2*)&Crow[(size_t)8 * ldr + cl] = v1;
        }
    }
}

// ======================= row softmax over g_S ==============================
__global__ void softmax_kernel()
{
    __shared__ float srow[kT];
    __shared__ float red[8];
    float* row = g_S + (size_t)blockIdx.x * kT;
    const float sc = 0.044194173824159216f;      // 512^-0.5
    const int w = threadIdx.x >> 5, lane = threadIdx.x & 31;

    float m = -1e30f;
    for (int l = threadIdx.x; l < kT / 4; l += 256) {
        float4 v = *(const float4*)&row[l * 4];
        v.x *= sc; v.y *= sc; v.z *= sc; v.w *= sc;
        *(float4*)&srow[l * 4] = v;
        m = fmaxf(m, fmaxf(fmaxf(v.x, v.y), fmaxf(v.z, v.w)));
    }
    for (int o = 16; o; o >>= 1) m = fmaxf(m, __shfl_xor_sync(0xffffffffu, m, o));
    if (lane == 0) red[w] = m;
    __syncthreads();
    m = red[0];
#pragma unroll
    for (int i = 1; i < 8; i++) m = fmaxf(m, red[i]);

    float s = 0.f;
    for (int l = threadIdx.x; l < kT / 4; l += 256) {
        float4 v = *(const float4*)&srow[l * 4];
        v.x = __expf(v.x - m); v.y = __expf(v.y - m);
        v.z = __expf(v.z - m); v.w = __expf(v.w - m);
        *(float4*)&srow[l * 4] = v;
        s += v.x + v.y + v.z + v.w;
    }
    for (int o = 16; o; o >>= 1) s += __shfl_xor_sync(0xffffffffu, s, o);
    __syncthreads();
    if (lane == 0) red[w] = s;
    __syncthreads();
    s = 0.f;
#pragma unroll
    for (int i = 0; i < 8; i++) s += red[i];
    const float inv = 1.f / s;

    for (int l = threadIdx.x; l < kT / 4; l += 256) {
        float4 v = *(const float4*)&srow[l * 4];
        v.x *= inv; v.y *= inv; v.z *= inv; v.w *= inv;
        *(float4*)&row[l * 4] = v;
    }
}

// ======================= launch ============================================
extern "C" void kernel_launch(void* const* d_in, const int* in_sizes, int n_in,
                              void* d_out, int out_size)
{
    const float* x      = (const float*)d_in[0];
    const float* gn_w   = (const float*)d_in[1];
    const float* gn_b   = (const float*)d_in[2];
    const float* qkv_w  = (const float*)d_in[3];
    const float* qkv_b  = (const float*)d_in[4];
    const float* proj_w = (const float*)d_in[5];
    const float* proj_b = (const float*)d_in[6];
    float* out = (float*)d_out;

    float *h, *qkv, *S, *o;
    cudaGetSymbolAddress((void**)&h,   g_h);
    cudaGetSymbolAddress((void**)&qkv, g_qkv);
    cudaGetSymbolAddress((void**)&S,   g_S);
    cudaGetSymbolAddress((void**)&o,   g_o);

    cudaFuncSetAttribute(mma_gemm<true, 3>,
        cudaFuncAttributeMaxDynamicSharedMemorySize, kSmemBytes);
    cudaFuncSetAttribute(mma_gemm<true, 0>,
        cudaFuncAttributeMaxDynamicSharedMemorySize, kSmemBytes);
    cudaFuncSetAttribute(mma_gemm<false, 2>,
        cudaFuncAttributeMaxDynamicSharedMemorySize, kSmemBytes);

    const size_t CT = (size_t)kC * kT;
    const size_t TT = (size_t)kT * kT;

    // 1) GroupNorm
    gn_stats_kernel<<<kNB * kG, 256>>>(x);
    gn_apply_kernel<<<((size_t)kNB * kC * kT / 4 + 255) / 256, 256>>>(x, gn_w, gn_b);

    // 2) QKV: rows 0-511 q (->[t][c]), 512-1023 k (->[c][t]), 1024-1535 v (->[t][c])
    mma_gemm<true, 3><<<dim3(kT / 128, 12, kNB), 256, kSmemBytes>>>(
        qkv_w, kC, 0, h, kT, CT, qkv, kT, 3 * CT, qkv_b, nullptr, kC);

    // 3) S[i][j] = sum_c qT[i][c] * k[c][j]
    mma_gemm<true, 0><<<dim3(kT / 128, kT / 128, kNB), 256, kSmemBytes>>>(
        qkv, kC, 3 * CT, qkv + CT, kT, 3 * CT, S, kT, TT, nullptr, nullptr, kC);

    // 4) softmax rows (scale fused)
    softmax_kernel<<<kNB * kT, 256>>>();

    // 5) o[q][c] = sum_t P[q][t] * vT[t][c]
    mma_gemm<true, 0><<<dim3(kC / 128, kT / 128, kNB), 256, kSmemBytes>>>(
        S, kT, TT, qkv + 2 * CT, kC, 3 * CT, o, kC, CT, nullptr, nullptr, kT);

    // 6) out[d][t] = x + proj_w[d][c] * o[t][c] + proj_b[d]   (B = o, [n][k])
    mma_gemm<false, 2><<<dim3(kT / 128, kC / 128, kNB), 256, kSmemBytes>>>(
        proj_w, kC, 0, o, kC, CT, out, kT, CT, proj_b, x, kC);
}

// round 7
// speedup vs baseline: 2.8249x; 1.0044x over previous
#include <cuda_runtime.h>
#include <cuda_bf16.h>
#include <cstdint>

// Problem constants: x [NB, C, H, W], T = H*W
constexpr int kNB  = 8;
constexpr int kC   = 512;
constexpr int kT   = 4096;
constexpr int kG   = 32;
constexpr int kCPG = kC / kG;
constexpr float kEPS = 1e-5f;

// -------------------- scratch (static .bss, no allocations) ----------------
__device__ float g_mean[kNB * kG];
__device__ float g_rstd[kNB * kG];
__device__ float g_h  [(size_t)kNB * kC * kT];          // normalized input [c][t]
// qkv: q TRANSPOSED [t][c] | k [c][t] | v TRANSPOSED [t][c]
__device__ float g_qkv[(size_t)kNB * 3 * kC * kT];
__device__ float g_S  [(size_t)kNB * kT * kT];          // logits / probs
__device__ float g_o  [(size_t)kNB * kC * kT];          // attn out [t][c]

// ======================= helpers ===========================================
__device__ __forceinline__ uint32_t smem_u32(const void* p) {
    uint32_t a;
    asm("{ .reg .u64 t; cvta.to.shared.u64 t, %1; cvt.u32.u64 %0, t; }"
        : "=r"(a) : "l"(p));
    return a;
}
__device__ __forceinline__ void ldsm4(uint32_t* r, uint32_t addr) {
    asm volatile("ldmatrix.sync.aligned.m8n8.x4.shared.b16 {%0,%1,%2,%3}, [%4];"
        : "=r"(r[0]), "=r"(r[1]), "=r"(r[2]), "=r"(r[3]) : "r"(addr));
}
__device__ __forceinline__ void ldsm4t(uint32_t* r, uint32_t addr) {
    asm volatile("ldmatrix.sync.aligned.m8n8.x4.trans.shared.b16 {%0,%1,%2,%3}, [%4];"
        : "=r"(r[0]), "=r"(r[1]), "=r"(r[2]), "=r"(r[3]) : "r"(addr));
}
__device__ __forceinline__ void mma16816(float* d, const uint32_t* a,
                                         uint32_t b0, uint32_t b1) {
    asm volatile("mma.sync.aligned.m16n8k16.row.col.f32.bf16.bf16.f32 "
        "{%0,%1,%2,%3}, {%4,%5,%6,%7}, {%8,%9}, {%0,%1,%2,%3};"
        : "+f"(d[0]), "+f"(d[1]), "+f"(d[2]), "+f"(d[3])
        : "r"(a[0]), "r"(a[1]), "r"(a[2]), "r"(a[3]), "r"(b0), "r"(b1));
}
// split fp32 float4 -> hi/lo bf16 quads at hp/lp (8B each)
__device__ __forceinline__ void cvt8(__nv_bfloat16* hp, __nv_bfloat16* lp, float4 v) {
    float2 v01{v.x, v.y}, v23{v.z, v.w};
    __nv_bfloat162 h01 = __float22bfloat162_rn(v01);
    __nv_bfloat162 h23 = __float22bfloat162_rn(v23);
    float2 l01{v.x - __bfloat162float(h01.x), v.y - __bfloat162float(h01.y)};
    float2 l23{v.z - __bfloat162float(h23.x), v.w - __bfloat162float(h23.y)};
    __nv_bfloat162 L01 = __float22bfloat162_rn(l01);
    __nv_bfloat162 L23 = __float22bfloat162_rn(l23);
    *(__nv_bfloat162*)hp       = h01;
    *(__nv_bfloat162*)(hp + 2) = h23;
    *(__nv_bfloat162*)lp       = L01;
    *(__nv_bfloat162*)(lp + 2) = L23;
}

// ======================= GroupNorm =========================================
__global__ void gn_stats_kernel(const float* __restrict__ x)
{
    const int b = blockIdx.x;
    const float4* p = (const float4*)(x + (size_t)b * (kCPG * kT));
    float s = 0.f, ss = 0.f;
    for (int l = threadIdx.x; l < kCPG * kT / 4; l += 256) {
        float4 v = p[l];
        s  += v.x + v.y + v.z + v.w;
        ss += v.x*v.x + v.y*v.y + v.z*v.z + v.w*v.w;
    }
    __shared__ float rs[8], rss[8];
    for (int o = 16; o; o >>= 1) {
        s  += __shfl_xor_sync(0xffffffffu, s,  o);
        ss += __shfl_xor_sync(0xffffffffu, ss, o);
    }
    const int w = threadIdx.x >> 5, lane = threadIdx.x & 31;
    if (lane == 0) { rs[w] = s; rss[w] = ss; }
    __syncthreads();
    if (threadIdx.x == 0) {
        float S = 0.f, SS = 0.f;
        for (int i = 0; i < 8; i++) { S += rs[i]; SS += rss[i]; }
        const float inv = 1.f / (kCPG * kT);
        const float m = S * inv;
        g_mean[b] = m;
        g_rstd[b] = rsqrtf(SS * inv - m * m + kEPS);
    }
}

__global__ void gn_apply_kernel(const float* __restrict__ x,
                                const float* __restrict__ gw,
                                const float* __restrict__ gb)
{
    const size_t f = (size_t)blockIdx.x * blockDim.x + threadIdx.x;
    const size_t e = f * 4;
    if (e >= (size_t)kNB * kC * kT) return;
    const int c = (int)((e / kT) % kC);
    const int b = (int)(e / ((size_t)kCPG * kT));
    const float r  = g_rstd[b];
    const float sc = gw[c] * r;
    const float sh = gb[c] - g_mean[b] * sc;
    float4 v = *(const float4*)(x + e);
    v.x = v.x * sc + sh; v.y = v.y * sc + sh;
    v.z = v.z * sc + sh; v.w = v.w * sc + sh;
    *(float4*)(g_h + e) = v;
}

// ======================= mma.sync GEMM =====================================
// D[128x128 tile] = A[m][k] * B;  A fp32 k-contig rows (lda).
//  BJC=true : B[k][n], n contiguous (ldb)
//  BJC=false: B[n][k], k contiguous (ldb)  (transposed into smem)
// EPI: 0 plain; 2 +bias[m]+resid; 3 QKV routing (q,v transposed via smem stage)
// smem per stage (bf16 elems): Ahi 128*40 | Alo | Bhi 32*136 | Blo
constexpr int kAW = 40, kBW = 136;
constexpr int kAhi = 0, kAlo = 5120, kBhi = 10240, kBlo = 14592;
constexpr int kSS  = 18944;                       // stage elems
constexpr int kSmemBytes = 2 * kSS * 2;           // 75776 B

template<bool BJC, int EPI>
__global__ __launch_bounds__(256)
void mma_gemm(const float* __restrict__ A, int lda, size_t sA,
              const float* __restrict__ B, int ldb, size_t sB,
              float* __restrict__ C, int ldc, size_t sC,
              const float* __restrict__ bias,
              const float* __restrict__ resid, int K)
{
    extern __shared__ char smem[];
    __nv_bfloat16* sb = (__nv_bfloat16*)smem;
    const uint32_t sbase = smem_u32(smem);

    const int tid = threadIdx.x;
    const int lane = tid & 31, wid = tid >> 5;
    const int wm = wid >> 1, wn = wid & 1;

    A += (size_t)blockIdx.z * sA;
    B += (size_t)blockIdx.z * sB;
    C += (size_t)blockIdx.z * sC;
    const int bi = blockIdx.y * 128, bj = blockIdx.x * 128;
    const float* Ab = A + (size_t)bi * lda;
    const float* Bb = BJC ? (B + bj) : (B + (size_t)bj * ldb);

    float acc[2][8][4];
#pragma unroll
    for (int m = 0; m < 2; m++)
#pragma unroll
        for (int n = 0; n < 8; n++)
#pragma unroll
            for (int q = 0; q < 4; q++) acc[m][n][q] = 0.f;

    float4 ar[4], br[4];

    auto ldgA = [&](int k0) {
#pragma unroll
        for (int j = 0; j < 4; j++) {
            const int idx = tid + j * 256, r = idx >> 3, kq = idx & 7;
            ar[j] = *(const float4*)&Ab[(size_t)r * lda + k0 + kq * 4];
        }
    };
    auto ldgB = [&](int k0) {
        if (BJC) {
#pragma unroll
            for (int j = 0; j < 4; j++) {
                const int idx = tid + j * 256, kr = idx >> 5, nq = idx & 31;
                br[j] = *(const float4*)&Bb[(size_t)(k0 + kr) * ldb + nq * 4];
            }
        } else {
            const int ng = tid >> 3, kq = tid & 7;
#pragma unroll
            for (int j = 0; j < 4; j++)
                br[j] = *(const float4*)&Bb[(size_t)(ng * 4 + j) * ldb + k0 + kq * 4];
        }
    };
    auto sts = [&](int buf) {
        __nv_bfloat16* ah = sb + buf * kSS + kAhi;
        __nv_bfloat16* al = sb + buf * kSS + kAlo;
        __nv_bfloat16* bh = sb + buf * kSS + kBhi;
        __nv_bfloat16* bl = sb + buf * kSS + kBlo;
#pragma unroll
        for (int j = 0; j < 4; j++) {
            const int idx = tid + j * 256, r = idx >> 3, kq = idx & 7;
            cvt8(ah + r * kAW + kq * 4, al + r * kAW + kq * 4, ar[j]);
        }
        if (BJC) {
#pragma unroll
            for (int j = 0; j < 4; j++) {
                const int idx = tid + j * 256, kr = idx >> 5, nq = idx & 31;
                cvt8(bh + kr * kBW + nq * 4, bl + kr * kBW + nq * 4, br[j]);
            }
        } else {
            const int ng = tid >> 3, kq = tid & 7;
            const float* f = (const float*)br;
#pragma unroll
            for (int c = 0; c < 4; c++) {
                float4 t{f[c], f[4 + c], f[8 + c], f[12 + c]};
                cvt8(bh + (kq * 4 + c) * kBW + ng * 4,
                     bl + (kq * 4 + c) * kBW + ng * 4, t);
            }
        }
    };
    auto compute = [&](int buf) {
        const uint32_t ah = sbase + (buf * kSS + kAhi) * 2;
        const uint32_t al = sbase + (buf * kSS + kAlo) * 2;
        const uint32_t bh = sbase + (buf * kSS + kBhi) * 2;
        const uint32_t bl = sbase + (buf * kSS + kBlo) * 2;
#pragma unroll
        for (int kk = 0; kk < 32; kk += 16) {
            uint32_t Ahf[2][4], Alf[2][4], Bhf[4][4], Blf[4][4];
            const int arow = wm * 32 + (lane & 15);
            const int acol = kk + (lane >> 4) * 8;
#pragma unroll
            for (int mt = 0; mt < 2; mt++) {
                const uint32_t off = ((arow + mt * 16) * kAW + acol) * 2;
                ldsm4(Ahf[mt], ah + off);
                ldsm4(Alf[mt], al + off);
            }
            const int brow = kk + (lane & 15);
            const int bcol = wn * 64 + (lane >> 4) * 8;
#pragma unroll
            for (int g = 0; g < 4; g++) {
                const uint32_t off = (brow * kBW + bcol + g * 16) * 2;
                ldsm4t(Bhf[g], bh + off);
                ldsm4t(Blf[g], bl + off);
            }
#pragma unroll
            for (int mt = 0; mt < 2; mt++)
#pragma unroll
                for (int nt = 0; nt < 8; nt++) {
                    const int g = nt >> 1, h = (nt & 1) * 2;
                    mma16816(acc[mt][nt], Ahf[mt], Bhf[g][h], Bhf[g][h + 1]);
                    mma16816(acc[mt][nt], Ahf[mt], Blf[g][h], Blf[g][h + 1]);
                    mma16816(acc[mt][nt], Alf[mt], Bhf[g][h], Bhf[g][h + 1]);
                }
        }
    };

    const int nst = K / 32;
    ldgA(0); ldgB(0); sts(0);
    __syncthreads();
    for (int s = 0; s < nst; ++s) {
        if (s + 1 < nst) { ldgA((s + 1) * 32); ldgB((s + 1) * 32); }
        compute(s & 1);
        __syncthreads();
        if (s + 1 < nst) { sts((s + 1) & 1); __syncthreads(); }
    }

    // ------------------- epilogue ------------------------------------------
    if (EPI == 3 && (bi < 512 || bi >= 1024)) {
        // q / v blocks: stage to smem, write transposed [t][c] coalesced
        float* sf = (float*)smem;                   // [col 128][136]
#pragma unroll
        for (int mt = 0; mt < 2; mt++) {
            const int rl = wm * 32 + mt * 16 + (lane >> 2);
            const float bv0 = bias[bi + rl], bv8 = bias[bi + rl + 8];
#pragma unroll
            for (int nt = 0; nt < 8; nt++) {
                const int cl = wn * 64 + nt * 8 + (lane & 3) * 2;
                sf[(size_t)cl * 136 + rl]            = acc[mt][nt][0] + bv0;
                sf[(size_t)(cl + 1) * 136 + rl]      = acc[mt][nt][1] + bv0;
                sf[(size_t)cl * 136 + rl + 8]        = acc[mt][nt][2] + bv8;
                sf[(size_t)(cl + 1) * 136 + rl + 8]  = acc[mt][nt][3] + bv8;
            }
        }
        __syncthreads();
        float* outT = (bi < 512) ? C : (C + 2 * (size_t)kC * kT);
        const int coff = (bi < 512) ? bi : (bi - 1024);
        for (int i2 = tid; i2 < 4096; i2 += 256) {
            const int j = i2 >> 5, rq = i2 & 31;
            float4 v = *(float4*)&sf[(size_t)j * 136 + rq * 4];
            *(float4*)&outT[(size_t)(bj + j) * kC + coff + rq * 4] = v;
        }
        return;
    }

#pragma unroll
    for (int mt = 0; mt < 2; mt++) {
        const int rl = wm * 32 + mt * 16 + (lane >> 2);
        float bv0 = 0.f, bv8 = 0.f;
        if (EPI == 2 || EPI == 3) { bv0 = bias[bi + rl]; bv8 = bias[bi + rl + 8]; }
        float* Crow;
        if (EPI == 3) {     // k block: [c][t] at C + CT, row = bi-512+rl
            Crow = C + (size_t)kC * kT + (size_t)(bi - 512 + rl) * kT + bj;
        } else {
            Crow = C + (size_t)(bi + rl) * ldc + bj;
        }
        const int ldr = (EPI == 3) ? kT : ldc;
#pragma unroll
        for (int nt = 0; nt < 8; nt++) {
            const int cl = wn * 64 + nt * 8 + (lane & 3) * 2;
            float2 v0{acc[mt][nt][0] + bv0, acc[mt][nt][1] + bv0};
            float2 v1{acc[mt][nt][2] + bv8, acc[mt][nt][3] + bv8};
            if (EPI == 2) {
                const float* rp = resid + (size_t)blockIdx.z * sC
                                + (size_t)(bi + rl) * ldc + bj;
                float2 r0 = *(const float2*)&rp[cl];
                float2 r1 = *(const float2*)&rp[(size_t)8 * ldc + cl];
                v0.x += r0.x; v0.y += r0.y; v1.x += r1.x; v1.y += r1.y;
            }
            *(float2*)&Crow[cl] = v0;
            *(float2*)&Crow[(size_t)8 * ldr + cl] = v1;
        }
    }
}

// ======================= row softmax over g_S ==============================
__global__ void softmax_kernel()
{
    __shared__ float srow[kT];
    __shared__ float red[8];
    float* row = g_S + (size_t)blockIdx.x * kT;
    const float sc = 0.044194173824159216f;      // 512^-0.5
    const int w = threadIdx.x >> 5, lane = threadIdx.x & 31;

    float m = -1e30f;
    for (int l = threadIdx.x; l < kT / 4; l += 256) {
        float4 v = *(const float4*)&row[l * 4];
        v.x *= sc; v.y *= sc; v.z *= sc; v.w *= sc;
        *(float4*)&srow[l * 4] = v;
        m = fmaxf(m, fmaxf(fmaxf(v.x, v.y), fmaxf(v.z, v.w)));
    }
    for (int o = 16; o; o >>= 1) m = fmaxf(m, __shfl_xor_sync(0xffffffffu, m, o));
    if (lane == 0) red[w] = m;
    __syncthreads();
    m = red[0];
#pragma unroll
    for (int i = 1; i < 8; i++) m = fmaxf(m, red[i]);

    float s = 0.f;
    for (int l = threadIdx.x; l < kT / 4; l += 256) {
        float4 v = *(const float4*)&srow[l * 4];
        v.x = __expf(v.x - m); v.y = __expf(v.y - m);
        v.z = __expf(v.z - m); v.w = __expf(v.w - m);
        *(float4*)&srow[l * 4] = v;
        s += v.x + v.y + v.z + v.w;
    }
    for (int o = 16; o; o >>= 1) s += __shfl_xor_sync(0xffffffffu, s, o);
    __syncthreads();
    if (lane == 0) red[w] = s;
    __syncthreads();
    s = 0.f;
#pragma unroll
    for (int i = 0; i < 8; i++) s += red[i];
    const float inv = 1.f / s;

    for (int l = threadIdx.x; l < kT / 4; l += 256) {
        float4 v = *(const float4*)&srow[l * 4];
        v.x *= inv; v.y *= inv; v.z *= inv; v.w *= inv;
        *(float4*)&row[l * 4] = v;
    }
}

// ======================= launch ============================================
extern "C" void kernel_launch(void* const* d_in, const int* in_sizes, int n_in,
                              void* d_out, int out_size)
{
    const float* x      = (const float*)d_in[0];
    const float* gn_w   = (const float*)d_in[1];
    const float* gn_b   = (const float*)d_in[2];
    const float* qkv_w  = (const float*)d_in[3];
    const float* qkv_b  = (const float*)d_in[4];
    const float* proj_w = (const float*)d_in[5];
    const float* proj_b = (const float*)d_in[6];
    float* out = (float*)d_out;

    float *h, *qkv, *S, *o;
    cudaGetSymbolAddress((void**)&h,   g_h);
    cudaGetSymbolAddress((void**)&qkv, g_qkv);
    cudaGetSymbolAddress((void**)&S,   g_S);
    cudaGetSymbolAddress((void**)&o,   g_o);

    cudaFuncSetAttribute(mma_gemm<true, 3>,
        cudaFuncAttributeMaxDynamicSharedMemorySize, kSmemBytes);
    cudaFuncSetAttribute(mma_gemm<true, 0>,
        cudaFuncAttributeMaxDynamicSharedMemorySize, kSmemBytes);
    cudaFuncSetAttribute(mma_gemm<false, 2>,
        cudaFuncAttributeMaxDynamicSharedMemorySize, kSmemBytes);

    const size_t CT = (size_t)kC * kT;
    const size_t TT = (size_t)kT * kT;

    // 1) GroupNorm
    gn_stats_kernel<<<kNB * kG, 256>>>(x);
    gn_apply_kernel<<<((size_t)kNB * kC * kT / 4 + 255) / 256, 256>>>(x, gn_w, gn_b);

    // 2) QKV: rows 0-511 q (->[t][c]), 512-1023 k (->[c][t]), 1024-1535 v (->[t][c])
    mma_gemm<true, 3><<<dim3(kT / 128, 12, kNB), 256, kSmemBytes>>>(
        qkv_w, kC, 0, h, kT, CT, qkv, kT, 3 * CT, qkv_b, nullptr, kC);

    // 3) S[i][j] = sum_c qT[i][c] * k[c][j]
    mma_gemm<true, 0><<<dim3(kT / 128, kT / 128, kNB), 256, kSmemBytes>>>(
        qkv, kC, 3 * CT, qkv + CT, kT, 3 * CT, S, kT, TT, nullptr, nullptr, kC);

    // 4) softmax rows (scale fused)
    softmax_kernel<<<kNB * kT, 256>>>();

    // 5) o[q][c] = sum_t P[q][t] * vT[t][c]
    mma_gemm<true, 0><<<dim3(kC / 128, kT / 128, kNB), 256, kSmemBytes>>>(
        S, kT, TT, qkv + 2 * CT, kC, 3 * CT, o, kC, CT, nullptr, nullptr, kT);

    // 6) out[d][t] = x + proj_w[d][c] * o[t][c] + proj_b[d]   (B = o, [n][k])
    mma_gemm<false, 2><<<dim3(kT / 128, kC / 128, kNB), 256, kSmemBytes>>>(
        proj_w, kC, 0, o, kC, CT, out, kT, CT, proj_b, x, kC);
}